// round 16
// baseline (speedup 1.0000x reference)
#include <cuda_runtime.h>
#include <cuda_fp16.h>
#include <stdint.h>
#include <math.h>

#define E 8
#define D 1024
#define H 4096
#define O 1024
#define NTOK 4096

// ---------------- scratch ----------------
__device__ int    d_counts[E];
__device__ int    d_offs[E];
__device__ int    d_tok[E * NTOK];
__device__ float  d_wt[E * NTOK];
__device__ __half d_xh[(size_t)NTOK * D];       // x in fp16
__device__ __half d_h[(size_t)2 * NTOK * H];    // gathered hidden, fp16
__device__ __half d_w1t[(size_t)E * H * D];     // W1^T fp16 [E,H,D]
__device__ __half d_w2t[(size_t)E * O * H];     // W2^T fp16 [E,O,H]

// ---------------- helpers ----------------
__device__ __forceinline__ uint32_t smem_u32(const void* p) {
    uint32_t a;
    asm("{ .reg .u64 t; cvta.to.shared.u64 t, %1; cvt.u32.u64 %0, t; }" : "=r"(a) : "l"(p));
    return a;
}
__device__ __forceinline__ void ldm_x4(uint32_t* d, uint32_t a) {
    asm volatile("ldmatrix.sync.aligned.m8n8.x4.shared.b16 {%0,%1,%2,%3}, [%4];"
                 : "=r"(d[0]), "=r"(d[1]), "=r"(d[2]), "=r"(d[3]) : "r"(a));
}
__device__ __forceinline__ void mma16816(float* c, const uint32_t* a, const uint32_t* b) {
    asm("mma.sync.aligned.m16n8k16.row.col.f32.f16.f16.f32 "
        "{%0,%1,%2,%3}, {%4,%5,%6,%7}, {%8,%9}, {%0,%1,%2,%3};"
        : "+f"(c[0]), "+f"(c[1]), "+f"(c[2]), "+f"(c[3])
        : "r"(a[0]), "r"(a[1]), "r"(a[2]), "r"(a[3]), "r"(b[0]), "r"(b[1]));
}
__device__ __forceinline__ uint32_t pack2h(float x0, float x1) {
    return ((uint32_t)__half_as_ushort(__float2half_rn(x1)) << 16)
         | __half_as_ushort(__float2half_rn(x0));
}
__device__ __forceinline__ void cp16(uint32_t dst, const void* src) {
    asm volatile("cp.async.cg.shared.global [%0], [%1], 16;" :: "r"(dst), "l"(src));
}
__device__ __forceinline__ void cp_commit() {
    asm volatile("cp.async.commit_group;" ::: "memory");
}
template <int N>
__device__ __forceinline__ void cp_wait() {
    asm volatile("cp.async.wait_group %0;" :: "n"(N) : "memory");
}

// ---------------- routing (+ fused x->fp16 conversion) ----------------
__global__ void zero_counts_kernel() {
    if (threadIdx.x < E) d_counts[threadIdx.x] = 0;
}

__global__ void gate_kernel(const float* __restrict__ x,
                            const float* __restrict__ Wg,
                            const float* __restrict__ bg) {
    int n = blockIdx.x;
    int tid = threadIdx.x;
    int w = tid >> 5;
    int lane = tid & 31;
    const float* xr = x + (size_t)n * D;

    float acc = 0.f;
    for (int d = lane; d < D; d += 32)
        acc += xr[d] * Wg[d * E + w];
    #pragma unroll
    for (int off = 16; off; off >>= 1)
        acc += __shfl_down_sync(0xffffffffu, acc, off);

    __shared__ float logits[E];
    if (lane == 0) logits[w] = acc + bg[w];

    // fused: x -> fp16
    {
        const float2* xr2 = (const float2*)xr;
        uint32_t* xo = (uint32_t*)(d_xh + (size_t)n * D);
        #pragma unroll
        for (int i = tid; i < D / 2; i += 256)
            xo[i] = pack2h(xr2[i].x, xr2[i].y);
    }
    __syncthreads();

    if (tid == 0) {
        int i0 = 0; float v0 = logits[0];
        #pragma unroll
        for (int e = 1; e < E; e++)
            if (logits[e] > v0) { v0 = logits[e]; i0 = e; }
        int i1 = -1; float v1 = -3.0e38f;
        #pragma unroll
        for (int e = 0; e < E; e++)
            if (e != i0 && logits[e] > v1) { v1 = logits[e]; i1 = e; }
        float w0 = 1.f / (1.f + expf(v1 - v0));
        float w1 = 1.f - w0;

        int p0 = atomicAdd(&d_counts[i0], 1);
        d_tok[i0 * NTOK + p0] = n;
        d_wt [i0 * NTOK + p0] = w0;

        int p1 = atomicAdd(&d_counts[i1], 1);
        d_tok[i1 * NTOK + p1] = n;
        d_wt [i1 * NTOK + p1] = w1;
    }
}

__global__ void scan_kernel() {
    if (threadIdx.x == 0) {
        int t = 0;
        #pragma unroll
        for (int e = 0; e < E; e++) { d_offs[e] = t; t += d_counts[e]; }
    }
}

__global__ void zero_out_kernel(float* __restrict__ out) {
    int i = blockIdx.x * blockDim.x + threadIdx.x;
    ((float4*)out)[i] = make_float4(0.f, 0.f, 0.f, 0.f);
}

// ---------------- prep: W [E][K][NOUT] f32 -> WT [E][NOUT][K] fp16 ----------------
// Output scratch referenced as device symbol INSIDE the kernel (host-passed
// __device__ symbol pointers are invalid -> the R3/R12 zero-weight bug).
template <bool FIRST>
__global__ void transpose_h_kernel(const float* __restrict__ in) {
    constexpr int Kd = FIRST ? D : H;
    constexpr int Nd = FIRST ? H : O;
    __half* out = FIRST ? d_w1t : d_w2t;
    __shared__ float t[32][33];
    int e = blockIdx.z;
    int n0 = blockIdx.x * 32, k0 = blockIdx.y * 32;
    int tx = threadIdx.x, ty = threadIdx.y;
    const float* ie = in + (size_t)e * Kd * Nd;
    #pragma unroll
    for (int i = 0; i < 32; i += 8)
        t[ty + i][tx] = ie[(size_t)(k0 + ty + i) * Nd + n0 + tx];
    __syncthreads();
    __half* oe = out + (size_t)e * Nd * Kd;
    #pragma unroll
    for (int i = 0; i < 32; i += 8)
        oe[(size_t)(n0 + ty + i) * Kd + k0 + tx] = __float2half_rn(t[tx][ty + i]);
}

// ---------------- HMMA grouped GEMM, cp.async 3-stage, K-chunk 64 ----------------
// Block tile 128x128x64, 256 threads = 8 warps (2m x 4n), warp tile 64x32.
// 144B row pitch (9*16B stagger -> conflict-free ldmatrix). 2 CTAs/SM.
#define PITCH 144
#define TILE_BYTES (128 * PITCH)           // 18432
#define STAGE_BYTES (2 * TILE_BYTES)       // A|B = 36864
#define NSTAGE 3

template <bool FIRST>
__global__ void __launch_bounds__(256, 2)
gemm_hmma(const float* __restrict__ bias, float* __restrict__ out) {
    const int e = blockIdx.z;
    const int C = d_counts[e];
    const int m0 = blockIdx.y * 128;
    if (m0 >= C) return;
    const int n0 = blockIdx.x * 128;
    constexpr int K = FIRST ? D : H;
    constexpr int NOUT = FIRST ? H : O;
    const int base = d_offs[e];

    extern __shared__ __align__(16) char smem[];
    const uint32_t sb = smem_u32(smem);

    const int tid = threadIdx.x;
    const int lane = tid & 31;
    const int wid = tid >> 5;
    const int warp_m = wid >> 2;     // 0..1
    const int warp_n = wid & 3;      // 0..3

    // staging: thread owns row lr (both A and B), 64B part hf
    const int lr = tid >> 1;
    const int hf = tid & 1;

    int mi = m0 + lr; if (mi > C - 1) mi = C - 1;
    const __half* arow = FIRST ? (d_xh + (size_t)d_tok[e * NTOK + mi] * D)
                               : (d_h + (size_t)(base + mi) * H);
    const __half* brow = (FIRST ? d_w1t : d_w2t) + ((size_t)e * NOUT + n0 + lr) * K;

    float acc[4][4][4] = {};

    auto issue = [&](int slot, int kb) {
        uint32_t dA = sb + (uint32_t)(slot * STAGE_BYTES) + (uint32_t)(lr * PITCH + hf * 64);
        const __half* sa = arow + kb + hf * 32;
        cp16(dA,      sa);
        cp16(dA + 16, sa + 8);
        cp16(dA + 32, sa + 16);
        cp16(dA + 48, sa + 24);
        uint32_t dB = dA + (uint32_t)TILE_BYTES;
        const __half* sbp = brow + kb + hf * 32;
        cp16(dB,      sbp);
        cp16(dB + 16, sbp + 8);
        cp16(dB + 32, sbp + 16);
        cp16(dB + 48, sbp + 24);
    };

    // ldmatrix addressing (144B pitch)
    const uint32_t a_lane_off = (uint32_t)((lane & 15) * PITCH + (lane >> 4) * 16)
                              + (uint32_t)(warp_m * 64 * PITCH);
    const uint32_t b_lane_off = (uint32_t)(((lane & 7) + (lane >> 4) * 8) * PITCH
                                           + ((lane >> 3) & 1) * 16)
                              + (uint32_t)(warp_n * 32 * PITCH);

    auto compute = [&](int slot) {
        const uint32_t sA = sb + (uint32_t)(slot * STAGE_BYTES);
        const uint32_t sB = sA + (uint32_t)TILE_BYTES;
        #pragma unroll
        for (int kh = 0; kh < 4; kh++) {
            const uint32_t kb = kh * 32;   // bytes: 16 elements per k-half
            uint32_t bh[2][4];
            uint32_t ah[4][4];
            #pragma unroll
            for (int p = 0; p < 2; p++)
                ldm_x4(bh[p], sB + b_lane_off + kb + (uint32_t)(p * 16 * PITCH));
            #pragma unroll
            for (int mt = 0; mt < 4; mt++)
                ldm_x4(ah[mt], sA + a_lane_off + kb + (uint32_t)(mt * 16 * PITCH));
            #pragma unroll
            for (int mt = 0; mt < 4; mt++)
                #pragma unroll
                for (int nt = 0; nt < 4; nt++)
                    mma16816(acc[mt][nt], ah[mt], &bh[nt >> 1][(nt & 1) * 2]);
        }
    };

    const int NCH = K / 64;
    issue(0, 0);  cp_commit();
    issue(1, 64); cp_commit();
    for (int c = 0; c < NCH; c++) {
        cp_wait<1>();            // chunk c complete
        __syncthreads();         // visible to all; prior compute on reused slot done
        if (c + 2 < NCH) issue((c + 2) % NSTAGE, (c + 2) * 64);
        cp_commit();
        compute(c % NSTAGE);
    }

    // ---------------- epilogue ----------------
    const int g = lane >> 2;
    const int t = lane & 3;
    #pragma unroll
    for (int mt = 0; mt < 4; mt++) {
        const int rw = warp_m * 64 + mt * 16 + g;
        #pragma unroll
        for (int hrow = 0; hrow < 2; hrow++) {
            const int m = m0 + rw + hrow * 8;
            if (m >= C) continue;
            #pragma unroll
            for (int nt = 0; nt < 4; nt++) {
                const int col = n0 + warp_n * 32 + nt * 8 + 2 * t;
                float v0 = acc[mt][nt][hrow * 2 + 0] + bias[e * NOUT + col];
                float v1 = acc[mt][nt][hrow * 2 + 1] + bias[e * NOUT + col + 1];
                if (FIRST) {
                    uint32_t hp = pack2h(fmaxf(v0, 0.f), fmaxf(v1, 0.f));
                    *(uint32_t*)(d_h + (size_t)(base + m) * H + col) = hp;
                } else {
                    // fused combine: two atomic adds per output element onto
                    // zero-initialized out (commutative -> deterministic).
                    float wt = d_wt[e * NTOK + m];
                    int tok = d_tok[e * NTOK + m];
                    float* op = out + (size_t)tok * O + col;
                    atomicAdd(op + 0, wt * v0);
                    atomicAdd(op + 1, wt * v1);
                }
            }
        }
    }
}

extern "C" void kernel_launch(void* const* d_in, const int* in_sizes, int n_in,
                              void* d_out, int out_size) {
    const float* x  = (const float*)d_in[0];
    const float* W1 = (const float*)d_in[1];
    const float* b1 = (const float*)d_in[2];
    const float* W2 = (const float*)d_in[3];
    const float* b2 = (const float*)d_in[4];
    const float* Wg = (const float*)d_in[5];
    const float* bg = (const float*)d_in[6];
    float* out = (float*)d_out;

    cudaFuncSetAttribute(gemm_hmma<true>,  cudaFuncAttributeMaxDynamicSharedMemorySize, NSTAGE * STAGE_BYTES);
    cudaFuncSetAttribute(gemm_hmma<false>, cudaFuncAttributeMaxDynamicSharedMemorySize, NSTAGE * STAGE_BYTES);

    zero_counts_kernel<<<1, 32>>>();
    gate_kernel<<<NTOK, 256>>>(x, Wg, bg);
    scan_kernel<<<1, 1>>>();
    zero_out_kernel<<<(NTOK * O / 4) / 256, 256>>>(out);

    transpose_h_kernel<true ><<<dim3(H / 32, D / 32, E), dim3(32, 8)>>>(W1);
    transpose_h_kernel<false><<<dim3(O / 32, H / 32, E), dim3(32, 8)>>>(W2);

    gemm_hmma<true ><<<dim3(H / 128, NTOK / 128, E), 256, NSTAGE * STAGE_BYTES>>>(b1, nullptr);
    gemm_hmma<false><<<dim3(O / 128, NTOK / 128, E), 256, NSTAGE * STAGE_BYTES>>>(b2, out);
}

// round 17
// speedup vs baseline: 1.2127x; 1.2127x over previous
#include <cuda_runtime.h>
#include <cuda_fp16.h>
#include <stdint.h>
#include <math.h>

#define E 8
#define D 1024
#define H 4096
#define O 1024
#define NTOK 4096

// ---------------- scratch ----------------
__device__ int    d_counts[E];
__device__ int    d_offs[E];
__device__ int    d_tok[E * NTOK];
__device__ float  d_wt[E * NTOK];
__device__ __half d_xh[(size_t)NTOK * D];       // x in fp16
__device__ __half d_h[(size_t)2 * NTOK * H];    // gathered hidden, fp16
__device__ __half d_w1t[(size_t)E * H * D];     // W1^T fp16 [E,H,D]
__device__ __half d_w2t[(size_t)E * O * H];     // W2^T fp16 [E,O,H]

// ---------------- helpers ----------------
__device__ __forceinline__ uint32_t smem_u32(const void* p) {
    uint32_t a;
    asm("{ .reg .u64 t; cvta.to.shared.u64 t, %1; cvt.u32.u64 %0, t; }" : "=r"(a) : "l"(p));
    return a;
}
__device__ __forceinline__ void ldm_x4(uint32_t* d, uint32_t a) {
    asm volatile("ldmatrix.sync.aligned.m8n8.x4.shared.b16 {%0,%1,%2,%3}, [%4];"
                 : "=r"(d[0]), "=r"(d[1]), "=r"(d[2]), "=r"(d[3]) : "r"(a));
}
__device__ __forceinline__ void mma16816(float* c, const uint32_t* a, const uint32_t* b) {
    asm("mma.sync.aligned.m16n8k16.row.col.f32.f16.f16.f32 "
        "{%0,%1,%2,%3}, {%4,%5,%6,%7}, {%8,%9}, {%0,%1,%2,%3};"
        : "+f"(c[0]), "+f"(c[1]), "+f"(c[2]), "+f"(c[3])
        : "r"(a[0]), "r"(a[1]), "r"(a[2]), "r"(a[3]), "r"(b[0]), "r"(b[1]));
}
__device__ __forceinline__ uint32_t pack2h(float x0, float x1) {
    return ((uint32_t)__half_as_ushort(__float2half_rn(x1)) << 16)
         | __half_as_ushort(__float2half_rn(x0));
}
__device__ __forceinline__ void cp16(uint32_t dst, const void* src) {
    asm volatile("cp.async.cg.shared.global [%0], [%1], 16;" :: "r"(dst), "l"(src));
}
__device__ __forceinline__ void cp_commit() {
    asm volatile("cp.async.commit_group;" ::: "memory");
}
template <int N>
__device__ __forceinline__ void cp_wait() {
    asm volatile("cp.async.wait_group %0;" :: "n"(N) : "memory");
}

// ---------------- routing (+ fused x->fp16 conversion + out zeroing) ----------------
__global__ void zero_counts_kernel() {
    if (threadIdx.x < E) d_counts[threadIdx.x] = 0;
}

__global__ void gate_kernel(const float* __restrict__ x,
                            const float* __restrict__ Wg,
                            const float* __restrict__ bg,
                            float* __restrict__ out) {
    int n = blockIdx.x;
    int tid = threadIdx.x;
    int w = tid >> 5;
    int lane = tid & 31;
    const float* xr = x + (size_t)n * D;

    float acc = 0.f;
    for (int d = lane; d < D; d += 32)
        acc += xr[d] * Wg[d * E + w];
    #pragma unroll
    for (int off = 16; off; off >>= 1)
        acc += __shfl_down_sync(0xffffffffu, acc, off);

    __shared__ float logits[E];
    if (lane == 0) logits[w] = acc + bg[w];

    // fused: x -> fp16 + zero out-row
    {
        const float2* xr2 = (const float2*)xr;
        uint32_t* xo = (uint32_t*)(d_xh + (size_t)n * D);
        #pragma unroll
        for (int i = tid; i < D / 2; i += 256)
            xo[i] = pack2h(xr2[i].x, xr2[i].y);
        ((float4*)(out + (size_t)n * O))[tid] = make_float4(0.f, 0.f, 0.f, 0.f);
    }
    __syncthreads();

    if (tid == 0) {
        int i0 = 0; float v0 = logits[0];
        #pragma unroll
        for (int e = 1; e < E; e++)
            if (logits[e] > v0) { v0 = logits[e]; i0 = e; }
        int i1 = -1; float v1 = -3.0e38f;
        #pragma unroll
        for (int e = 0; e < E; e++)
            if (e != i0 && logits[e] > v1) { v1 = logits[e]; i1 = e; }
        float w0 = 1.f / (1.f + expf(v1 - v0));
        float w1 = 1.f - w0;

        int p0 = atomicAdd(&d_counts[i0], 1);
        d_tok[i0 * NTOK + p0] = n;
        d_wt [i0 * NTOK + p0] = w0;

        int p1 = atomicAdd(&d_counts[i1], 1);
        d_tok[i1 * NTOK + p1] = n;
        d_wt [i1 * NTOK + p1] = w1;
    }
}

__global__ void scan_kernel() {
    if (threadIdx.x == 0) {
        int t = 0;
        #pragma unroll
        for (int e = 0; e < E; e++) { d_offs[e] = t; t += d_counts[e]; }
    }
}

// ---------------- prep: W [E][K][NOUT] f32 -> WT [E][NOUT][K] fp16 ----------------
// 128(k) x 32(n) tiles: fp16 writes in 256B-contiguous uint4 runs per n-row.
// Output scratch referenced as device symbol INSIDE the kernel (host-passed
// __device__ symbol pointers are invalid -> the R3/R12 zero-weight bug).
template <bool FIRST>
__global__ void __launch_bounds__(256) transpose_h_kernel(const float* __restrict__ in) {
    constexpr int Kd = FIRST ? D : H;
    constexpr int Nd = FIRST ? H : O;
    __half* out = FIRST ? d_w1t : d_w2t;
    __shared__ float t[128][33];
    int e = blockIdx.z;
    int n0 = blockIdx.x * 32, k0 = blockIdx.y * 128;
    int tx = threadIdx.x & 31, ty = threadIdx.x >> 5;   // tx: n, ty: k-group
    const float* ie = in + (size_t)e * Kd * Nd;
    #pragma unroll
    for (int i = 0; i < 16; i++)
        t[ty + i * 8][tx] = ie[(size_t)(k0 + ty + i * 8) * Nd + n0 + tx];
    __syncthreads();
    __half* oe = out + (size_t)e * Nd * Kd;
    #pragma unroll
    for (int it = 0; it < 2; it++) {
        int unit = threadIdx.x + it * 256;
        int n = unit >> 4;            // 0..31
        int kq = unit & 15;           // 0..15, 8 k's each
        uint32_t p[4];
        #pragma unroll
        for (int j = 0; j < 4; j++)
            p[j] = pack2h(t[kq * 8 + 2 * j][n], t[kq * 8 + 2 * j + 1][n]);
        *(uint4*)(oe + (size_t)(n0 + n) * Kd + k0 + kq * 8) =
            make_uint4(p[0], p[1], p[2], p[3]);
    }
}

// ---------------- HMMA grouped GEMM, cp.async 4-stage (R15 config, 674us) ----------------
// Block tile 128x128x32, 256 threads = 8 warps (2m x 4n), warp tile 64x32.
// Plain fp16 MMA, pure cp.async.cg staging. 2 CTAs/SM.
#define SROW 40
#define TILE_BYTES (128 * SROW * 2)        // 10240
#define STAGE_BYTES (2 * TILE_BYTES)       // A|B = 20480
#define NSTAGE 4

template <bool FIRST>
__global__ void __launch_bounds__(256, 2)
gemm_hmma(const float* __restrict__ bias, float* __restrict__ out) {
    const int e = blockIdx.z;
    const int C = d_counts[e];
    const int m0 = blockIdx.y * 128;
    if (m0 >= C) return;
    const int n0 = blockIdx.x * 128;
    constexpr int K = FIRST ? D : H;
    constexpr int NOUT = FIRST ? H : O;
    const int base = d_offs[e];

    extern __shared__ __align__(16) char smem[];
    const uint32_t sb = smem_u32(smem);

    const int tid = threadIdx.x;
    const int lane = tid & 31;
    const int wid = tid >> 5;
    const int warp_m = wid >> 2;     // 0..1
    const int warp_n = wid & 3;      // 0..3

    // staging: thread owns row lr (both A and B), 32B part hf
    const int lr = tid >> 1;
    const int hf = tid & 1;

    int mi = m0 + lr; if (mi > C - 1) mi = C - 1;
    const __half* arow = FIRST ? (d_xh + (size_t)d_tok[e * NTOK + mi] * D)
                               : (d_h + (size_t)(base + mi) * H);
    const __half* brow = (FIRST ? d_w1t : d_w2t) + ((size_t)e * NOUT + n0 + lr) * K;

    float acc[4][4][4] = {};

    auto issue = [&](int slot, int kb) {
        uint32_t dA = sb + (uint32_t)(slot * STAGE_BYTES) + (uint32_t)(lr * 80 + hf * 32);
        const __half* sa = arow + kb + hf * 16;
        cp16(dA, sa);
        cp16(dA + 16, sa + 8);
        uint32_t dB = dA + (uint32_t)TILE_BYTES;
        const __half* sbp = brow + kb + hf * 16;
        cp16(dB, sbp);
        cp16(dB + 16, sbp + 8);
    };

    // ldmatrix addressing (validated layout, 80B pitch)
    const uint32_t a_lane_off = (uint32_t)((lane & 15) * (SROW * 2) + (lane >> 4) * 16)
                              + (uint32_t)(warp_m * 64 * SROW * 2);
    const uint32_t b_lane_off = (uint32_t)(((lane & 7) + (lane >> 4) * 8) * (SROW * 2)
                                           + ((lane >> 3) & 1) * 16)
                              + (uint32_t)(warp_n * 32 * SROW * 2);

    auto compute = [&](int slot) {
        const uint32_t sA = sb + (uint32_t)(slot * STAGE_BYTES);
        const uint32_t sB = sA + (uint32_t)TILE_BYTES;
        #pragma unroll
        for (int kh = 0; kh < 2; kh++) {
            const uint32_t kb = kh * 32;
            uint32_t bh[2][4];
            uint32_t ah[4][4];
            #pragma unroll
            for (int p = 0; p < 2; p++)
                ldm_x4(bh[p], sB + b_lane_off + kb + (uint32_t)(p * 16 * SROW * 2));
            #pragma unroll
            for (int mt = 0; mt < 4; mt++)
                ldm_x4(ah[mt], sA + a_lane_off + kb + (uint32_t)(mt * 16 * SROW * 2));
            #pragma unroll
            for (int mt = 0; mt < 4; mt++)
                #pragma unroll
                for (int nt = 0; nt < 4; nt++)
                    mma16816(acc[mt][nt], ah[mt], &bh[nt >> 1][(nt & 1) * 2]);
        }
    };

    const int NCH = K / 32;
    issue(0, 0);  cp_commit();
    issue(1, 32); cp_commit();
    issue(2, 64); cp_commit();
    for (int c = 0; c < NCH; c++) {
        cp_wait<2>();            // chunk c complete (<=2 younger groups pending)
        __syncthreads();         // visible to all; prior compute on reused slot done
        if (c + 3 < NCH) issue((c + 3) % NSTAGE, (c + 3) * 32);
        cp_commit();
        compute(c % NSTAGE);
    }

    // ---------------- epilogue ----------------
    const int g = lane >> 2;
    const int t = lane & 3;
    #pragma unroll
    for (int mt = 0; mt < 4; mt++) {
        const int rw = warp_m * 64 + mt * 16 + g;
        #pragma unroll
        for (int hrow = 0; hrow < 2; hrow++) {
            const int m = m0 + rw + hrow * 8;
            if (m >= C) continue;
            #pragma unroll
            for (int nt = 0; nt < 4; nt++) {
                const int col = n0 + warp_n * 32 + nt * 8 + 2 * t;
                float v0 = acc[mt][nt][hrow * 2 + 0] + bias[e * NOUT + col];
                float v1 = acc[mt][nt][hrow * 2 + 1] + bias[e * NOUT + col + 1];
                if (FIRST) {
                    uint32_t hp = pack2h(fmaxf(v0, 0.f), fmaxf(v1, 0.f));
                    *(uint32_t*)(d_h + (size_t)(base + m) * H + col) = hp;
                } else {
                    // fused combine: two atomic adds per output element onto
                    // zero-initialized out (commutative -> deterministic).
                    float wt = d_wt[e * NTOK + m];
                    int tok = d_tok[e * NTOK + m];
                    float* op = out + (size_t)tok * O + col;
                    atomicAdd(op + 0, wt * v0);
                    atomicAdd(op + 1, wt * v1);
                }
            }
        }
    }
}

extern "C" void kernel_launch(void* const* d_in, const int* in_sizes, int n_in,
                              void* d_out, int out_size) {
    const float* x  = (const float*)d_in[0];
    const float* W1 = (const float*)d_in[1];
    const float* b1 = (const float*)d_in[2];
    const float* W2 = (const float*)d_in[3];
    const float* b2 = (const float*)d_in[4];
    const float* Wg = (const float*)d_in[5];
    const float* bg = (const float*)d_in[6];
    float* out = (float*)d_out;

    cudaFuncSetAttribute(gemm_hmma<true>,  cudaFuncAttributeMaxDynamicSharedMemorySize, NSTAGE * STAGE_BYTES);
    cudaFuncSetAttribute(gemm_hmma<false>, cudaFuncAttributeMaxDynamicSharedMemorySize, NSTAGE * STAGE_BYTES);

    zero_counts_kernel<<<1, 32>>>();
    gate_kernel<<<NTOK, 256>>>(x, Wg, bg, out);
    scan_kernel<<<1, 1>>>();

    transpose_h_kernel<true ><<<dim3(H / 32, D / 128, E), 256>>>(W1);
    transpose_h_kernel<false><<<dim3(O / 32, H / 128, E), 256>>>(W2);

    gemm_hmma<true ><<<dim3(H / 128, NTOK / 128, E), 256, NSTAGE * STAGE_BYTES>>>(b1, nullptr);
    gemm_hmma<false><<<dim3(O / 128, NTOK / 128, E), 256, NSTAGE * STAGE_BYTES>>>(b2, out);
}